// round 6
// baseline (speedup 1.0000x reference)
#include <cuda_runtime.h>
#include <stdint.h>

// Problem constants
#define BB 16
#define NN 25200
#define CC 80
#define MAXDET 100

// Bucketed hi-subset (exact prefix of greedy; fallback guards all tails)
#define T_BKT 0.95f
#define NB 128               // buckets over [0.95, 1.0)
#define BSCALE 2560.0f       // NB / 0.05
#define BCAP 32              // per-bucket capacity (lambda ~9.8)
#define SCAP 2048            // sorted stream capacity (expected ~1260)
#define WIN 128              // walk window width

// Fallback full list
#define CAP_S 13312
#define KS 13

// Output layout (flattened concat, float32):
#define OFF_BOX   0
#define OFF_SCORE 6400
#define OFF_CLS   8000
#define OFF_CNT   136000

typedef unsigned long long ull;

// ---------------- scratch (__device__ globals: no allocs) -------------------
// zero-initialized at module load; every kernel_launch leaves counters zeroed.
__device__ ull    g_bkey[BB][NB][BCAP];
__device__ float4 g_bcor[BB][NB][BCAP];
__device__ int    g_bcnt[BB][NB];
__device__ int    g_bovf[BB];
__device__ int    g_done[BB];
__device__ float4 g_cor[BB][NN];      // fallback-only
__device__ float2 g_meta[BB][NN];     // fallback-only
__device__ float4 g_selbox[BB][MAXDET];
__device__ float  g_selscore[BB][MAXDET];
__device__ int    g_selidx[BB][MAXDET];

// identical IOU expression everywhere (proven bit-exact vs reference)
__device__ __forceinline__ bool iou_conflict(float4 A, float aA, float4 B2, float aB)
{
    float ltx = fmaxf(A.x, B2.x);
    float lty = fmaxf(A.y, B2.y);
    float rbx = fminf(A.z, B2.z);
    float rby = fminf(A.w, B2.w);
    float w = fmaxf(rbx - ltx, 0.0f);
    float h = fmaxf(rby - lty, 0.0f);
    float inter = w * h;
    float denom = aA + aB - inter + 1e-9f;
    return inter > 0.5f * denom;
}

// ---------------------------------------------------------------------------
// Kernel 1: bucket compaction of score >= T_BKT only (hot path needs nothing
// else). Bucket map monotone in score; u64 key = (score desc, idx asc).
// ---------------------------------------------------------------------------
__global__ void __launch_bounds__(256)
compact_kernel(const float* __restrict__ boxes, const float* __restrict__ obj)
{
    const int b = blockIdx.y;
    const int n = blockIdx.x * 256 + threadIdx.x;

    float sc = 0.0f;
    bool p = false;
    if (n < NN) {
        sc = obj[(size_t)b * NN + n];
        p = (sc >= T_BKT);
    }
    if (p) {
        const float4* bx4 = reinterpret_cast<const float4*>(boxes);
        float4 v = bx4[(size_t)b * NN + n];        // (x, y, w, h)
        float hx = 0.5f * v.z;
        float hy = 0.5f * v.w;
        float4 cor = make_float4(v.x - hx, v.y - hy, v.x + hx, v.y + hy);

        int bk = (int)((sc - T_BKT) * BSCALE);
        bk = bk > (NB - 1) ? (NB - 1) : (bk < 0 ? 0 : bk);
        int pos = atomicAdd(&g_bcnt[b][bk], 1);
        if (pos < BCAP) {
            g_bkey[b][bk][pos] = ((ull)__float_as_uint(sc) << 32)
                               | (ull)(0xFFFFFFFFu - (unsigned)n);
            g_bcor[b][bk][pos] = cor;
        } else {
            g_bovf[b] = 1;
        }
    }
}

// ---------------------------------------------------------------------------
// Kernel 2: sort + windowed lazy greedy walk + fused output write (done path).
// Self-cleans bucket counters/flags for the next graph replay.
// Dynamic smem: skey ull[SCAP] + scor float4[SCAP] = 48KB.
// ---------------------------------------------------------------------------
extern __shared__ ull dyn_smem[];

__global__ void __launch_bounds__(1024, 1)
nms_sorted_kernel(const float* __restrict__ class_prob, float* __restrict__ out)
{
    const int b    = blockIdx.x;
    const int tid  = threadIdx.x;
    const int wid  = tid >> 5;
    const int lane = tid & 31;

    ull*    skey = dyn_smem;                    // [SCAP]
    float4* scor = (float4*)(dyn_smem + SCAP);  // [SCAP]

    __shared__ int      s_cnt[NB];
    __shared__ int      s_off[NB];
    __shared__ int      s_ws[4];
    __shared__ int      s_len;
    __shared__ int      s_ovf;
    __shared__ unsigned srow[WIN][4];           // pairwise conflict rows
    __shared__ unsigned sconfA[4];              // conflict-vs-accepted bitmap
    __shared__ int      winPos[MAXDET];
    __shared__ int      s_accN;

    // ---- load + self-clean counters -----------------------------------------
    if (tid < NB) {
        s_cnt[tid] = g_bcnt[b][tid];
        g_bcnt[b][tid] = 0;
    }
    if (tid == 0) {
        s_ovf = g_bovf[b];
        g_bovf[b] = 0;
        g_done[b] = 0;
        s_accN = 0;
    }
    __syncthreads();
    if (s_ovf) return;                          // fallback handles (done=0)

    // ---- offsets: descending-bucket exclusive scan --------------------------
    int x = 0, v = 0;
    if (tid < NB) {
        v = s_cnt[NB - 1 - tid];
        x = v;
        #pragma unroll
        for (int o = 1; o < 32; o <<= 1) {
            int y = __shfl_up_sync(0xffffffffu, x, o);
            if (lane >= o) x += y;
        }
        if (lane == 31) s_ws[wid] = x;
    }
    __syncthreads();
    if (tid < NB) {
        int add = 0;
        #pragma unroll
        for (int w = 0; w < 4; w++) if (w < wid) add += s_ws[w];
        int incl = x + add;
        s_off[NB - 1 - tid] = incl - v;
        if (tid == NB - 1) s_len = incl;
    }
    __syncthreads();

    const int streamLen = s_len;
    if (streamLen > SCAP) return;               // fallback handles

    // ---- phase 1: per-bucket in-warp bitonic sort32 -> sorted stream --------
    for (int bk = wid; bk < NB; bk += 32) {
        int n = s_cnt[bk];
        if (n == 0) continue;
        ull k = (lane < n) ? ~g_bkey[b][bk][lane] : ~0ull;   // asc(~key) == key desc
        int pv0 = lane;
        int pv = pv0;
        #pragma unroll
        for (int sz = 2; sz <= 32; sz <<= 1) {
            #pragma unroll
            for (int j = sz >> 1; j > 0; j >>= 1) {
                ull pk = __shfl_xor_sync(0xffffffffu, k, j);
                int pw = __shfl_xor_sync(0xffffffffu, pv, j);
                bool up = ((lane & sz) == 0);
                bool takeMax = (((lane & j) != 0) == up);
                bool take = takeMax ? (pk > k) : (pk < k);
                if (take) { k = pk; pv = pw; }
            }
        }
        if (lane < n) {
            int o = s_off[bk] + lane;
            skey[o] = ~k;
            scor[o] = g_bcor[b][bk][pv];
        }
    }
    __syncthreads();

    // ---- phase 2: windowed exact greedy walk --------------------------------
    const int r  = tid >> 3;          // 0..127 (window row)
    const int g8 = tid & 7;           // 0..7
    int accN = 0;

    for (int base = 0; base < streamLen && accN < MAXDET; base += WIN) {
        const int wcnt = (streamLen - base < WIN) ? (streamLen - base) : WIN;

        if (tid < 4) sconfA[tid] = 0;
        __syncthreads();

        bool rvalid = (r < wcnt);
        float4 cr = rvalid ? scor[base + r] : make_float4(0.f, 0.f, 0.f, 0.f);
        float  ar = (cr.z - cr.x) * (cr.w - cr.y);

        // pairwise rows: thread computes 16 cols of its row
        unsigned bits = 0u;
        if (rvalid) {
            int c0 = g8 * 16;
            #pragma unroll
            for (int j = 0; j < 16; j++) {
                int col = c0 + j;
                if (col < wcnt && col != r) {
                    float4 cc = scor[base + col];
                    float ac = (cc.z - cc.x) * (cc.w - cc.y);
                    if (iou_conflict(cr, ar, cc, ac)) bits |= (1u << j);
                }
            }
        }
        unsigned hibits = __shfl_down_sync(0xffffffffu, bits, 1);
        if ((g8 & 1) == 0) srow[r][g8 >> 1] = bits | (hibits << 16);

        // conflict vs previously accepted winners
        bool conf = false;
        if (rvalid) {
            for (int a = g8; a < accN; a += 8) {
                float4 W = scor[winPos[a]];
                float Wa = (W.z - W.x) * (W.w - W.y);
                if (iou_conflict(W, Wa, cr, ar)) conf = true;
            }
        }
        unsigned bl = __ballot_sync(0xffffffffu, conf);
        if ((lane & 7) == 0) {
            if (((bl >> lane) & 0xffu) != 0u)
                atomicOr(&sconfA[r >> 5], 1u << (r & 31));
        }
        __syncthreads();

        // serial exact walk over the window (single thread, precomputed rows)
        if (tid == 0) {
            unsigned alive[4];
            #pragma unroll
            for (int w2 = 0; w2 < 4; w2++) alive[w2] = ~sconfA[w2];
            int acc = accN;
            for (int i = 0; i < wcnt && acc < MAXDET; i++) {
                if ((alive[i >> 5] >> (i & 31)) & 1u) {
                    winPos[acc++] = base + i;
                    #pragma unroll
                    for (int w2 = 0; w2 < 4; w2++) alive[w2] &= ~srow[i][w2];
                }
            }
            s_accN = acc;
        }
        __syncthreads();
        accN = s_accN;
    }

    if (accN != MAXDET) return;                 // done stays 0 -> fallback
    if (tid == 0) g_done[b] = 1;

    // ---- fused output write (done path: exactly MAXDET winners) -------------
    for (int i = wid; i < MAXDET; i += 32) {
        int pos = winPos[i];
        ull k = skey[pos];
        int orig = (int)(0xFFFFFFFFu - (unsigned)k);
        if (lane == 0) {
            float4 c = scor[pos];
            float* p = out + OFF_BOX + (size_t)(b * MAXDET + i) * 4;
            p[0] = c.x; p[1] = c.y; p[2] = c.z; p[3] = c.w;
            out[OFF_SCORE + b * MAXDET + i] =
                __uint_as_float((unsigned)(k >> 32));
        }
        const float* cp = class_prob + ((size_t)b * NN + orig) * CC;
        float* co = out + OFF_CLS + (size_t)(b * MAXDET + i) * CC;
        #pragma unroll
        for (int c2 = lane; c2 < CC; c2 += 32) co[c2] = cp[c2];
    }
    if (tid == 0) out[OFF_CNT + b] = (float)MAXDET;
}

// ---------------------------------------------------------------------------
// Kernel 3: exact fallback. Guarded by done; recompacts from raw inputs,
// runs the proven R3 round machinery, writes outputs itself.
// ---------------------------------------------------------------------------
extern __shared__ float4 sm4[];

__global__ void __launch_bounds__(1024, 1)
nms_fallback_kernel(const float* __restrict__ boxes, const float* __restrict__ obj,
                    const float* __restrict__ class_prob, float* __restrict__ out)
{
    const int b = blockIdx.x;
    if (g_done[b]) return;

    const int tid  = threadIdx.x;
    const int wid  = tid >> 5;
    const int lane = tid & 31;

    __shared__ ull  s_wkey[32];
    __shared__ int  s_wslot[32];
    __shared__ ull  s_winkey;
    __shared__ int  s_winslot;
    __shared__ float4 s_ovfbox;
    __shared__ int  s_base;

    // ---- unordered compaction from raw inputs (tie-breaks inside keys) ------
    if (tid == 0) s_base = 0;
    __syncthreads();
    const float4* bx4 = reinterpret_cast<const float4*>(boxes);
    for (int st = 0; st < NN; st += 1024) {
        int n = st + tid;
        bool p = false;
        float sc = 0.0f;
        if (n < NN) {
            sc = obj[(size_t)b * NN + n];
            p = (sc >= 0.5f);
        }
        unsigned ball = __ballot_sync(0xffffffffu, p);
        int basew = 0;
        if (lane == 0 && ball) basew = atomicAdd(&s_base, __popc(ball));
        basew = __shfl_sync(0xffffffffu, basew, 0);
        if (p) {
            float4 vv = bx4[(size_t)b * NN + n];
            float hx = 0.5f * vv.z;
            float hy = 0.5f * vv.w;
            int pos = basew + __popc(ball & ((1u << lane) - 1u));
            g_cor[b][pos]  = make_float4(vv.x - hx, vv.y - hy, vv.x + hx, vv.y + hy);
            g_meta[b][pos] = make_float2(sc, __int_as_float(n));
        }
    }
    __syncthreads();
    const int cnt = s_base;

    // ---- load into smem/registers -------------------------------------------
    ull key[KS];
    unsigned mask = 0u;
    #pragma unroll
    for (int k = 0; k < KS; k++) {
        int slot = (k << 10) + tid;
        key[k] = 0ull;
        if (slot < cnt) {
            sm4[slot] = g_cor[b][slot];
            float2 m = g_meta[b][slot];
            key[k] = ((ull)__float_as_uint(m.x) << 32)
                   | (ull)(0xFFFFFFFFu - __float_as_uint(m.y));
            mask |= (1u << k);
        } else {
            sm4[slot] = make_float4(0.f, 0.f, 0.f, 0.f);
        }
    }
    unsigned mask2 = 0u;
    const int kg_max = (cnt > CAP_S) ? ((cnt - CAP_S + 1023) >> 10) : 0;
    for (int kg = 0; kg < kg_max; kg++) {
        if (CAP_S + (kg << 10) + tid < cnt) mask2 |= (1u << kg);
    }
    __syncthreads();

    float4 W = make_float4(2.f, 2.f, 2.f, 2.f);
    float Wa = 0.f;
    int ndet = 0;

    for (int it = 0; it < MAXDET; it++) {
        ull bk = 0ull;
        int bslot = 0;

        #pragma unroll
        for (int k = 0; k < KS; k++) {
            int slot = (k << 10) + tid;
            float4 c = sm4[slot];
            float a2 = (c.z - c.x) * (c.w - c.y);
            if (iou_conflict(W, Wa, c, a2)) mask &= ~(1u << k);
            if (((mask >> k) & 1u) && key[k] > bk) { bk = key[k]; bslot = slot; }
        }
        for (int kg = 0; kg < kg_max; kg++) {
            if ((mask2 >> kg) & 1u) {
                int slot = CAP_S + (kg << 10) + tid;
                float4 c = g_cor[b][slot];
                float a2 = (c.z - c.x) * (c.w - c.y);
                if (iou_conflict(W, Wa, c, a2)) {
                    mask2 &= ~(1u << kg);
                } else {
                    float2 m = g_meta[b][slot];
                    ull kk = ((ull)__float_as_uint(m.x) << 32)
                           | (ull)(0xFFFFFFFFu - __float_as_uint(m.y));
                    if (kk > bk) { bk = kk; bslot = slot; }
                }
            }
        }

        #pragma unroll
        for (int off = 16; off; off >>= 1) {
            ull ok = __shfl_down_sync(0xffffffffu, bk, off);
            int os = __shfl_down_sync(0xffffffffu, bslot, off);
            if (ok > bk) { bk = ok; bslot = os; }
        }
        if (lane == 0) { s_wkey[wid] = bk; s_wslot[wid] = bslot; }
        __syncthreads();

        if (wid == 0) {
            ull k2 = s_wkey[lane];
            int sl2 = s_wslot[lane];
            #pragma unroll
            for (int off = 16; off; off >>= 1) {
                ull ok = __shfl_down_sync(0xffffffffu, k2, off);
                int os = __shfl_down_sync(0xffffffffu, sl2, off);
                if (ok > k2) { k2 = ok; sl2 = os; }
            }
            if (lane == 0) { s_winkey = k2; s_winslot = sl2; }
        }
        __syncthreads();

        const ull wk = s_winkey;
        if (wk == 0ull) break;
        const int ws = s_winslot;

        if (ws < CAP_S) {
            W = sm4[ws];
        } else {
            if ((ws & 1023) == tid) s_ovfbox = g_cor[b][ws];
            __syncthreads();
            W = s_ovfbox;
        }
        Wa = (W.z - W.x) * (W.w - W.y);
        ndet = it + 1;

        if (tid == 0) {
            g_selbox[b][it]   = W;
            g_selscore[b][it] = __uint_as_float((unsigned)(wk >> 32));
            g_selidx[b][it]   = (int)(0xFFFFFFFFu - (unsigned)wk);
        }
        if ((ws & 1023) == tid) {
            if (ws < CAP_S) mask  &= ~(1u << (ws >> 10));
            else            mask2 &= ~(1u << ((ws - CAP_S) >> 10));
        }
    }
    __syncthreads();

    // ---- output write (cold path, zero-fills past ndet) ----------------------
    for (int i = wid; i < MAXDET; i += 32) {
        bool valid = (i < ndet);
        float4 box = make_float4(0.f, 0.f, 0.f, 0.f);
        float scv = 0.0f;
        int orig = 0;
        if (valid) {
            box  = g_selbox[b][i];
            scv  = g_selscore[b][i];
            orig = g_selidx[b][i];
        }
        if (lane == 0) {
            float* p = out + OFF_BOX + (size_t)(b * MAXDET + i) * 4;
            p[0] = box.x; p[1] = box.y; p[2] = box.z; p[3] = box.w;
            out[OFF_SCORE + b * MAXDET + i] = scv;
        }
        const float* cp = class_prob + ((size_t)b * NN + orig) * CC;
        float* co = out + OFF_CLS + (size_t)(b * MAXDET + i) * CC;
        #pragma unroll
        for (int c2 = lane; c2 < CC; c2 += 32) {
            co[c2] = valid ? cp[c2] : 0.0f;
        }
    }
    if (tid == 0) out[OFF_CNT + b] = (float)ndet;
}

// ---------------------------------------------------------------------------
extern "C" void kernel_launch(void* const* d_in, const int* in_sizes, int n_in,
                              void* d_out, int out_size)
{
    const float* boxes = (const float*)d_in[0];   // (16, 25200, 4)
    const float* obj   = (const float*)d_in[1];   // (16, 25200, 1)
    const float* cls   = (const float*)d_in[2];   // (16, 25200, 80)
    float* out = (float*)d_out;

    const int sortedSmem = SCAP * (int)(sizeof(ull) + sizeof(float4));  // 48KB
    const int fbSmem     = CAP_S * (int)sizeof(float4);                 // 208KB

    static bool attr_done = false;
    if (!attr_done) {
        cudaFuncSetAttribute(nms_sorted_kernel,
                             cudaFuncAttributeMaxDynamicSharedMemorySize,
                             sortedSmem);
        cudaFuncSetAttribute(nms_fallback_kernel,
                             cudaFuncAttributeMaxDynamicSharedMemorySize,
                             fbSmem);
        attr_done = true;
    }

    compact_kernel<<<dim3((NN + 255) / 256, BB), 256>>>(boxes, obj);
    nms_sorted_kernel<<<BB, 1024, sortedSmem>>>(cls, out);
    nms_fallback_kernel<<<BB, 1024, fbSmem>>>(boxes, obj, cls, out);
}

// round 7
// speedup vs baseline: 1.0464x; 1.0464x over previous
#include <cuda_runtime.h>
#include <stdint.h>

// Problem constants
#define BB 16
#define NN 25200
#define NV 6300              // NN / 4
#define CC 80
#define MAXDET 100

// Bucketed hi-subset (exact prefix of greedy; inline fallback guards tails)
#define T_BKT 0.95f
#define NB 128               // buckets over [0.95, 1.0)
#define BSCALE 2560.0f       // NB / 0.05
#define BCAP 32              // per-bucket capacity (lambda ~9.8)
#define SCAP 2048            // sorted stream capacity (expected ~1260)
#define WIN 128              // walk window width

// Fallback full list
#define CAP_S 13312
#define KS 13

// Output layout (flattened concat, float32):
#define OFF_BOX   0
#define OFF_SCORE 6400
#define OFF_CLS   8000
#define OFF_CNT   136000

typedef unsigned long long ull;

// ---------------- scratch (__device__ globals: fallback-only) ---------------
__device__ float4 g_cor[BB][NN];
__device__ float2 g_meta[BB][NN];

// identical IOU expression everywhere (proven bit-exact vs reference)
__device__ __forceinline__ bool iou_conflict(float4 A, float aA, float4 B2, float aB)
{
    float ltx = fmaxf(A.x, B2.x);
    float lty = fmaxf(A.y, B2.y);
    float rbx = fminf(A.z, B2.z);
    float rby = fminf(A.w, B2.w);
    float w = fmaxf(rbx - ltx, 0.0f);
    float h = fmaxf(rby - lty, 0.0f);
    float inter = w * h;
    float denom = aA + aB - inter + 1e-9f;
    return inter > 0.5f * denom;
}

// Dynamic smem, two aliased layouts:
//  hot:      skey ull[SCAP] | scor float4[SCAP] | bkey ull[NB*BCAP]   (80KB)
//  fallback: sm4 float4[CAP_S]                                        (208KB)
extern __shared__ ull dyn_smem[];

__global__ void __launch_bounds__(1024, 1)
nms_fused_kernel(const float* __restrict__ boxes, const float* __restrict__ obj,
                 const float* __restrict__ class_prob, float* __restrict__ out)
{
    const int b    = blockIdx.x;
    const int tid  = threadIdx.x;
    const int wid  = tid >> 5;
    const int lane = tid & 31;

    ull*    skey = dyn_smem;                             // [SCAP]
    float4* scor = (float4*)(dyn_smem + SCAP);           // [SCAP]
    ull*    bkey = (ull*)(scor + SCAP);                  // [NB*BCAP]

    __shared__ int      s_cnt[NB];
    __shared__ int      s_off[NB];
    __shared__ int      s_ws[4];
    __shared__ int      s_len;
    __shared__ int      s_bad;
    __shared__ unsigned srow[WIN][4];
    __shared__ unsigned sconfA[4];
    __shared__ int      winPos[MAXDET];
    __shared__ int      s_accN;

    const float4* bx4  = reinterpret_cast<const float4*>(boxes) + (size_t)b * NN;
    const float4* obj4 = reinterpret_cast<const float4*>(obj) + (size_t)b * NV;

    // ================= phase A: smem bucket compaction =======================
    if (tid < NB) s_cnt[tid] = 0;
    if (tid == 0) { s_bad = 0; s_accN = 0; }
    __syncthreads();

    for (int i = tid; i < NV; i += 1024) {
        float4 s4 = obj4[i];
        #pragma unroll
        for (int j = 0; j < 4; j++) {
            float sc = (j == 0) ? s4.x : (j == 1) ? s4.y : (j == 2) ? s4.z : s4.w;
            if (sc >= T_BKT) {
                int n = i * 4 + j;
                int bk = (int)((sc - T_BKT) * BSCALE);
                bk = bk > (NB - 1) ? (NB - 1) : (bk < 0 ? 0 : bk);
                int pos = atomicAdd(&s_cnt[bk], 1);
                if (pos < BCAP) {
                    bkey[bk * BCAP + pos] = ((ull)__float_as_uint(sc) << 32)
                                          | (ull)(0xFFFFFFFFu - (unsigned)n);
                } else {
                    s_bad = 1;
                }
            }
        }
    }
    __syncthreads();

    bool needFallback = (s_bad != 0);

    // ================= phase B: descending-bucket offsets ====================
    int x = 0, v = 0;
    if (tid < NB) {
        v = s_cnt[NB - 1 - tid];
        x = v;
        #pragma unroll
        for (int o = 1; o < 32; o <<= 1) {
            int y = __shfl_up_sync(0xffffffffu, x, o);
            if (lane >= o) x += y;
        }
        if (lane == 31) s_ws[wid] = x;
    }
    __syncthreads();
    if (tid < NB) {
        int add = 0;
        #pragma unroll
        for (int w = 0; w < 4; w++) if (w < wid) add += s_ws[w];
        int incl = x + add;
        s_off[NB - 1 - tid] = incl - v;
        if (tid == NB - 1) s_len = incl;
    }
    __syncthreads();

    const int streamLen = s_len;
    needFallback = needFallback || (streamLen > SCAP);

    if (!needFallback) {
        // ============ phase C: per-bucket in-warp bitonic sort32 =============
        for (int bk = wid; bk < NB; bk += 32) {
            int n = s_cnt[bk];
            if (n == 0) continue;
            ull k = (lane < n) ? ~bkey[bk * BCAP + lane] : ~0ull; // asc(~k)==desc(k)
            #pragma unroll
            for (int sz = 2; sz <= 32; sz <<= 1) {
                #pragma unroll
                for (int j = sz >> 1; j > 0; j >>= 1) {
                    ull pk = __shfl_xor_sync(0xffffffffu, k, j);
                    bool up = ((lane & sz) == 0);
                    bool takeMax = (((lane & j) != 0) == up);
                    if (takeMax ? (pk > k) : (pk < k)) k = pk;
                }
            }
            if (lane < n) skey[s_off[bk] + lane] = ~k;
        }
        __syncthreads();

        // ============ phase D: gather + convert corners for the stream ======
        for (int i = tid; i < streamLen; i += 1024) {
            int idx = (int)(0xFFFFFFFFu - (unsigned)skey[i]);
            float4 vv = bx4[idx];                       // (x, y, w, h)
            float hx = 0.5f * vv.z;
            float hy = 0.5f * vv.w;
            scor[i] = make_float4(vv.x - hx, vv.y - hy, vv.x + hx, vv.y + hy);
        }
        __syncthreads();

        // ============ phase E: windowed exact greedy walk ====================
        const int r  = tid >> 3;      // 0..127 (window row)
        const int g8 = tid & 7;       // 0..7
        int accN = 0;

        for (int base = 0; base < streamLen && accN < MAXDET; base += WIN) {
            const int wcnt = (streamLen - base < WIN) ? (streamLen - base) : WIN;

            if (tid < 4) sconfA[tid] = 0;
            __syncthreads();

            bool rvalid = (r < wcnt);
            float4 cr = rvalid ? scor[base + r] : make_float4(0.f, 0.f, 0.f, 0.f);
            float  ar = (cr.z - cr.x) * (cr.w - cr.y);

            unsigned bits = 0u;
            if (rvalid) {
                int c0 = g8 * 16;
                #pragma unroll
                for (int j = 0; j < 16; j++) {
                    int col = c0 + j;
                    if (col < wcnt && col != r) {
                        float4 cc = scor[base + col];
                        float ac = (cc.z - cc.x) * (cc.w - cc.y);
                        if (iou_conflict(cr, ar, cc, ac)) bits |= (1u << j);
                    }
                }
            }
            unsigned hibits = __shfl_down_sync(0xffffffffu, bits, 1);
            if ((g8 & 1) == 0) srow[r][g8 >> 1] = bits | (hibits << 16);

            bool conf = false;
            if (rvalid) {
                for (int a = g8; a < accN; a += 8) {
                    float4 W = scor[winPos[a]];
                    float Wa = (W.z - W.x) * (W.w - W.y);
                    if (iou_conflict(W, Wa, cr, ar)) conf = true;
                }
            }
            unsigned bl = __ballot_sync(0xffffffffu, conf);
            if ((lane & 7) == 0) {
                if (((bl >> lane) & 0xffu) != 0u)
                    atomicOr(&sconfA[r >> 5], 1u << (r & 31));
            }
            __syncthreads();

            if (tid == 0) {
                unsigned alive[4];
                #pragma unroll
                for (int w2 = 0; w2 < 4; w2++) alive[w2] = ~sconfA[w2];
                int acc = accN;
                for (int i = 0; i < wcnt && acc < MAXDET; i++) {
                    if ((alive[i >> 5] >> (i & 31)) & 1u) {
                        winPos[acc++] = base + i;
                        #pragma unroll
                        for (int w2 = 0; w2 < 4; w2++) alive[w2] &= ~srow[i][w2];
                    }
                }
                s_accN = acc;
            }
            __syncthreads();
            accN = s_accN;
        }

        if (accN == MAXDET) {
            // ============ phase F: fused output write (hot path) =============
            for (int i = wid; i < MAXDET; i += 32) {
                int pos = winPos[i];
                ull k = skey[pos];
                int orig = (int)(0xFFFFFFFFu - (unsigned)k);
                if (lane == 0) {
                    float4 c = scor[pos];
                    float* p = out + OFF_BOX + (size_t)(b * MAXDET + i) * 4;
                    p[0] = c.x; p[1] = c.y; p[2] = c.z; p[3] = c.w;
                    out[OFF_SCORE + b * MAXDET + i] =
                        __uint_as_float((unsigned)(k >> 32));
                }
                const float* cp = class_prob + ((size_t)b * NN + orig) * CC;
                float* co = out + OFF_CLS + (size_t)(b * MAXDET + i) * CC;
                #pragma unroll
                for (int c2 = lane; c2 < CC; c2 += 32) co[c2] = cp[c2];
            }
            if (tid == 0) out[OFF_CNT + b] = (float)MAXDET;
            return;
        }
        needFallback = true;
        __syncthreads();      // everyone done reading hot-path smem
    }

    // ===================== inline exact fallback =============================
    // (statistically never taken; recomputes everything from raw inputs)
    {
        float4* sm4 = (float4*)dyn_smem;     // aliases the hot layout (208KB)

        __shared__ ull  s_wkey[32];
        __shared__ int  s_wslot[32];
        __shared__ ull  s_winkey;
        __shared__ int  s_winslot;
        __shared__ float4 s_ovfbox;
        __shared__ int  s_base;

        if (tid == 0) s_base = 0;
        __syncthreads();
        for (int st = 0; st < NN; st += 1024) {
            int n = st + tid;
            bool p = false;
            float sc = 0.0f;
            if (n < NN) {
                sc = obj[(size_t)b * NN + n];
                p = (sc >= 0.5f);
            }
            unsigned ball = __ballot_sync(0xffffffffu, p);
            int basew = 0;
            if (lane == 0 && ball) basew = atomicAdd(&s_base, __popc(ball));
            basew = __shfl_sync(0xffffffffu, basew, 0);
            if (p) {
                float4 vv = bx4[n];
                float hx = 0.5f * vv.z;
                float hy = 0.5f * vv.w;
                int pos = basew + __popc(ball & ((1u << lane) - 1u));
                g_cor[b][pos]  = make_float4(vv.x - hx, vv.y - hy, vv.x + hx, vv.y + hy);
                g_meta[b][pos] = make_float2(sc, __int_as_float(n));
            }
        }
        __syncthreads();
        const int cnt = s_base;

        ull key[KS];
        unsigned mask = 0u;
        #pragma unroll
        for (int k = 0; k < KS; k++) {
            int slot = (k << 10) + tid;
            key[k] = 0ull;
            if (slot < cnt) {
                sm4[slot] = g_cor[b][slot];
                float2 m = g_meta[b][slot];
                key[k] = ((ull)__float_as_uint(m.x) << 32)
                       | (ull)(0xFFFFFFFFu - __float_as_uint(m.y));
                mask |= (1u << k);
            } else {
                sm4[slot] = make_float4(0.f, 0.f, 0.f, 0.f);
            }
        }
        unsigned mask2 = 0u;
        const int kg_max = (cnt > CAP_S) ? ((cnt - CAP_S + 1023) >> 10) : 0;
        for (int kg = 0; kg < kg_max; kg++) {
            if (CAP_S + (kg << 10) + tid < cnt) mask2 |= (1u << kg);
        }
        __syncthreads();

        float4 W = make_float4(2.f, 2.f, 2.f, 2.f);
        float Wa = 0.f;
        int ndet = 0;

        for (int it = 0; it < MAXDET; it++) {
            ull bk2 = 0ull;
            int bslot = 0;

            #pragma unroll
            for (int k = 0; k < KS; k++) {
                int slot = (k << 10) + tid;
                float4 c = sm4[slot];
                float a2 = (c.z - c.x) * (c.w - c.y);
                if (iou_conflict(W, Wa, c, a2)) mask &= ~(1u << k);
                if (((mask >> k) & 1u) && key[k] > bk2) { bk2 = key[k]; bslot = slot; }
            }
            for (int kg = 0; kg < kg_max; kg++) {
                if ((mask2 >> kg) & 1u) {
                    int slot = CAP_S + (kg << 10) + tid;
                    float4 c = g_cor[b][slot];
                    float a2 = (c.z - c.x) * (c.w - c.y);
                    if (iou_conflict(W, Wa, c, a2)) {
                        mask2 &= ~(1u << kg);
                    } else {
                        float2 m = g_meta[b][slot];
                        ull kk = ((ull)__float_as_uint(m.x) << 32)
                               | (ull)(0xFFFFFFFFu - __float_as_uint(m.y));
                        if (kk > bk2) { bk2 = kk; bslot = slot; }
                    }
                }
            }

            #pragma unroll
            for (int off = 16; off; off >>= 1) {
                ull ok = __shfl_down_sync(0xffffffffu, bk2, off);
                int os = __shfl_down_sync(0xffffffffu, bslot, off);
                if (ok > bk2) { bk2 = ok; bslot = os; }
            }
            if (lane == 0) { s_wkey[wid] = bk2; s_wslot[wid] = bslot; }
            __syncthreads();

            if (wid == 0) {
                ull k2 = s_wkey[lane];
                int sl2 = s_wslot[lane];
                #pragma unroll
                for (int off = 16; off; off >>= 1) {
                    ull ok = __shfl_down_sync(0xffffffffu, k2, off);
                    int os = __shfl_down_sync(0xffffffffu, sl2, off);
                    if (ok > k2) { k2 = ok; sl2 = os; }
                }
                if (lane == 0) { s_winkey = k2; s_winslot = sl2; }
            }
            __syncthreads();

            const ull wk = s_winkey;
            if (wk == 0ull) break;
            const int ws = s_winslot;

            if (ws < CAP_S) {
                W = sm4[ws];
            } else {
                if ((ws & 1023) == tid) s_ovfbox = g_cor[b][ws];
                __syncthreads();
                W = s_ovfbox;
            }
            Wa = (W.z - W.x) * (W.w - W.y);
            ndet = it + 1;

            if (tid == 0) {
                // reuse winPos/skey areas? no: write straight to out at end;
                // stash in static smem via winPos + s_wkey trick is messy ->
                // write directly to global out here (cold path).
                float* p = out + OFF_BOX + (size_t)(b * MAXDET + it) * 4;
                p[0] = W.x; p[1] = W.y; p[2] = W.z; p[3] = W.w;
                out[OFF_SCORE + b * MAXDET + it] =
                    __uint_as_float((unsigned)(wk >> 32));
                winPos[it] = (int)(0xFFFFFFFFu - (unsigned)wk);   // orig idx
            }
            if ((ws & 1023) == tid) {
                if (ws < CAP_S) mask  &= ~(1u << (ws >> 10));
                else            mask2 &= ~(1u << ((ws - CAP_S) >> 10));
            }
        }
        __syncthreads();

        // classes + zero-fill (cold path)
        for (int i = wid; i < MAXDET; i += 32) {
            bool valid = (i < ndet);
            int orig = valid ? winPos[i] : 0;
            if (!valid && lane == 0) {
                float* p = out + OFF_BOX + (size_t)(b * MAXDET + i) * 4;
                p[0] = 0.f; p[1] = 0.f; p[2] = 0.f; p[3] = 0.f;
                out[OFF_SCORE + b * MAXDET + i] = 0.0f;
            }
            const float* cp = class_prob + ((size_t)b * NN + orig) * CC;
            float* co = out + OFF_CLS + (size_t)(b * MAXDET + i) * CC;
            #pragma unroll
            for (int c2 = lane; c2 < CC; c2 += 32) {
                co[c2] = valid ? cp[c2] : 0.0f;
            }
        }
        if (tid == 0) out[OFF_CNT + b] = (float)ndet;
    }
}

// ---------------------------------------------------------------------------
extern "C" void kernel_launch(void* const* d_in, const int* in_sizes, int n_in,
                              void* d_out, int out_size)
{
    const float* boxes = (const float*)d_in[0];   // (16, 25200, 4)
    const float* obj   = (const float*)d_in[1];   // (16, 25200, 1)
    const float* cls   = (const float*)d_in[2];   // (16, 25200, 80)
    float* out = (float*)d_out;

    const int fbSmem  = CAP_S * (int)sizeof(float4);                  // 208KB
    const int hotSmem = SCAP * (int)(sizeof(ull) + sizeof(float4))
                      + NB * BCAP * (int)sizeof(ull);                 // 80KB
    const int smem = (fbSmem > hotSmem) ? fbSmem : hotSmem;

    static bool attr_done = false;
    if (!attr_done) {
        cudaFuncSetAttribute(nms_fused_kernel,
                             cudaFuncAttributeMaxDynamicSharedMemorySize, smem);
        attr_done = true;
    }

    nms_fused_kernel<<<BB, 1024, smem>>>(boxes, obj, cls, out);
}

// round 8
// speedup vs baseline: 1.2022x; 1.1489x over previous
#include <cuda_runtime.h>
#include <stdint.h>

// Problem constants
#define BB 16
#define NN 25200
#define NV 6300              // NN / 4
#define CC 80
#define MAXDET 100

// Bucketed hi-subset (exact prefix of greedy; inline fallback guards tails)
#define T_BKT 0.95f
#define NB 128               // buckets over [0.95, 1.0)
#define BSCALE 2560.0f       // NB / 0.05
#define BCAP 32              // per-bucket capacity (lambda ~9.8)
#define SCAP 2048            // sorted stream capacity (expected ~1260)
#define WIN 128              // walk window width

// Fallback full list
#define CAP_S 13312
#define KS 13

// Output layout (flattened concat, float32):
#define OFF_BOX   0
#define OFF_SCORE 6400
#define OFF_CLS   8000
#define OFF_CNT   136000

typedef unsigned long long ull;

// ---------------- scratch (__device__ globals: fallback-only) ---------------
__device__ float4 g_cor[BB][NN];
__device__ float2 g_meta[BB][NN];

// identical IOU expression everywhere (proven bit-exact vs reference)
__device__ __forceinline__ bool iou_conflict(float4 A, float aA, float4 B2, float aB)
{
    float ltx = fmaxf(A.x, B2.x);
    float lty = fmaxf(A.y, B2.y);
    float rbx = fminf(A.z, B2.z);
    float rby = fminf(A.w, B2.w);
    float w = fmaxf(rbx - ltx, 0.0f);
    float h = fmaxf(rby - lty, 0.0f);
    float inter = w * h;
    float denom = aA + aB - inter + 1e-9f;
    return inter > 0.5f * denom;
}

// Dynamic smem, two aliased layouts:
//  hot:      skey ull[SCAP] | scor float4[SCAP] | sarea float[SCAP]
//            | bkey ull[NB*BCAP]                                  (~88KB)
//  fallback: sm4 float4[CAP_S]                                    (208KB)
extern __shared__ ull dyn_smem[];

__global__ void __launch_bounds__(1024, 1)
nms_fused_kernel(const float* __restrict__ boxes, const float* __restrict__ obj,
                 const float* __restrict__ class_prob, float* __restrict__ out)
{
    const int b    = blockIdx.x;
    const int tid  = threadIdx.x;
    const int wid  = tid >> 5;
    const int lane = tid & 31;

    ull*    skey  = dyn_smem;                            // [SCAP]
    float4* scor  = (float4*)(dyn_smem + SCAP);          // [SCAP]
    float*  sarea = (float*)(scor + SCAP);               // [SCAP]
    ull*    bkey  = (ull*)(sarea + SCAP);                // [NB*BCAP]

    __shared__ int      s_cnt[NB];
    __shared__ int      s_off[NB];
    __shared__ int      s_ws[4];
    __shared__ int      s_len;
    __shared__ int      s_bad;
    __shared__ unsigned srow[WIN][4];
    __shared__ unsigned sconfA[4];
    __shared__ int      winPos[MAXDET];
    __shared__ float4   acor[MAXDET];
    __shared__ float    aarea[MAXDET];
    __shared__ int      s_accN;

    const float4* bx4  = reinterpret_cast<const float4*>(boxes) + (size_t)b * NN;
    const float4* obj4 = reinterpret_cast<const float4*>(obj) + (size_t)b * NV;

    // ================= phase A: smem bucket compaction =======================
    if (tid < NB) s_cnt[tid] = 0;
    if (tid == 0) { s_bad = 0; s_accN = 0; }
    __syncthreads();

    for (int i = tid; i < NV; i += 1024) {
        float4 s4 = obj4[i];
        #pragma unroll
        for (int j = 0; j < 4; j++) {
            float sc = (j == 0) ? s4.x : (j == 1) ? s4.y : (j == 2) ? s4.z : s4.w;
            if (sc >= T_BKT) {
                int n = i * 4 + j;
                int bk = (int)((sc - T_BKT) * BSCALE);
                bk = bk > (NB - 1) ? (NB - 1) : (bk < 0 ? 0 : bk);
                int pos = atomicAdd(&s_cnt[bk], 1);
                if (pos < BCAP) {
                    bkey[bk * BCAP + pos] = ((ull)__float_as_uint(sc) << 32)
                                          | (ull)(0xFFFFFFFFu - (unsigned)n);
                } else {
                    s_bad = 1;
                }
            }
        }
    }
    __syncthreads();

    bool needFallback = (s_bad != 0);

    // ================= phase B: descending-bucket offsets ====================
    int x = 0, v = 0;
    if (tid < NB) {
        v = s_cnt[NB - 1 - tid];
        x = v;
        #pragma unroll
        for (int o = 1; o < 32; o <<= 1) {
            int y = __shfl_up_sync(0xffffffffu, x, o);
            if (lane >= o) x += y;
        }
        if (lane == 31) s_ws[wid] = x;
    }
    __syncthreads();
    if (tid < NB) {
        int add = 0;
        #pragma unroll
        for (int w = 0; w < 4; w++) if (w < wid) add += s_ws[w];
        int incl = x + add;
        s_off[NB - 1 - tid] = incl - v;
        if (tid == NB - 1) s_len = incl;
    }
    __syncthreads();

    const int streamLen = s_len;
    needFallback = needFallback || (streamLen > SCAP);

    if (!needFallback) {
        // ============ phase C: per-bucket in-warp bitonic sort32 =============
        for (int bk = wid; bk < NB; bk += 32) {
            int n = s_cnt[bk];
            if (n == 0) continue;
            ull k = (lane < n) ? ~bkey[bk * BCAP + lane] : ~0ull; // asc(~k)==desc(k)
            #pragma unroll
            for (int sz = 2; sz <= 32; sz <<= 1) {
                #pragma unroll
                for (int j = sz >> 1; j > 0; j >>= 1) {
                    ull pk = __shfl_xor_sync(0xffffffffu, k, j);
                    bool up = ((lane & sz) == 0);
                    bool takeMax = (((lane & j) != 0) == up);
                    if (takeMax ? (pk > k) : (pk < k)) k = pk;
                }
            }
            if (lane < n) skey[s_off[bk] + lane] = ~k;
        }
        __syncthreads();

        // ============ phase D: gather corners + precompute areas =============
        for (int i = tid; i < streamLen; i += 1024) {
            int idx = (int)(0xFFFFFFFFu - (unsigned)skey[i]);
            float4 vv = bx4[idx];                       // (x, y, w, h)
            float hx = 0.5f * vv.z;
            float hy = 0.5f * vv.w;
            float4 c = make_float4(vv.x - hx, vv.y - hy, vv.x + hx, vv.y + hy);
            scor[i] = c;
            sarea[i] = (c.z - c.x) * (c.w - c.y);
        }
        __syncthreads();

        // ============ phase E: alive-filtered windowed greedy walk ===========
        const int r  = tid >> 3;      // 0..127 (window row)
        const int g8 = tid & 7;       // 0..7
        int accN = 0;

        for (int base = 0; base < streamLen && accN < MAXDET; base += WIN) {
            const int wcnt = (streamLen - base < WIN) ? (streamLen - base) : WIN;

            // clear per-window state
            if (tid < 4) sconfA[tid] = 0;
            if (tid < 512) srow[tid >> 2][tid & 3] = 0;
            __syncthreads();

            const bool rvalid = (r < wcnt);
            float4 cr = make_float4(0.f, 0.f, 0.f, 0.f);
            float  ar = 0.0f;
            if (rvalid) { cr = scor[base + r]; ar = sarea[base + r]; }

            // -- pass 1: conflicts vs previously accepted (8 threads/row) -----
            bool conf = false;
            if (rvalid) {
                for (int a = g8; a < accN; a += 8) {
                    if (iou_conflict(acor[a], aarea[a], cr, ar)) conf = true;
                }
            }
            unsigned bl = __ballot_sync(0xffffffffu, conf);
            if ((lane & 7) == 0) {
                if (((bl >> lane) & 0xffu) != 0u)
                    atomicOr(&sconfA[r >> 5], 1u << (r & 31));
            }
            __syncthreads();

            // -- alive bitmap into registers (dead = conflicted OR >= wcnt) ---
            unsigned dead[4];
            #pragma unroll
            for (int w2 = 0; w2 < 4; w2++) {
                unsigned vm;                            // validity of 32 cols
                int lo = w2 << 5;
                if (wcnt >= lo + 32) vm = 0xffffffffu;
                else if (wcnt <= lo) vm = 0u;
                else vm = (1u << (wcnt - lo)) - 1u;
                dead[w2] = sconfA[w2] | ~vm;
            }
            const bool ralive = rvalid && !((dead[r >> 5] >> (r & 31)) & 1u);

            // -- pass 2: pairwise rows, alive x alive only --------------------
            unsigned bits = 0u;
            if (ralive) {
                int c0 = g8 * 16;
                #pragma unroll
                for (int j = 0; j < 16; j++) {
                    int col = c0 + j;
                    if (!((dead[col >> 5] >> (col & 31)) & 1u) && col != r) {
                        if (iou_conflict(cr, ar, scor[base + col], sarea[base + col]))
                            bits |= (1u << j);
                    }
                }
                if (bits)
                    atomicOr(&srow[r][g8 >> 1], bits << ((g8 & 1) * 16));
            }
            __syncthreads();

            // -- serial exact resolve over alive bits (single thread) ---------
            if (tid == 0) {
                unsigned alive[4];
                #pragma unroll
                for (int w2 = 0; w2 < 4; w2++) alive[w2] = ~dead[w2];
                int acc = accN;
                #pragma unroll
                for (int w2 = 0; w2 < 4; w2++) {
                    unsigned a = alive[w2];
                    while (a && acc < MAXDET) {
                        int bit = __ffs(a) - 1;
                        a &= a - 1;
                        int i = (w2 << 5) + bit;
                        // accept i
                        int sp = base + i;
                        winPos[acc] = sp;
                        acor[acc] = scor[sp];
                        aarea[acc] = sarea[sp];
                        acc++;
                        a &= ~srow[i][w2];
                        for (int w3 = w2 + 1; w3 < 4; w3++)
                            alive[w3] &= ~srow[i][w3];
                    }
                    if (acc >= MAXDET) break;
                }
                s_accN = acc;
            }
            __syncthreads();
            accN = s_accN;
        }

        if (accN == MAXDET) {
            // ============ phase F: fused output write (hot path) =============
            for (int i = wid; i < MAXDET; i += 32) {
                int pos = winPos[i];
                ull k = skey[pos];
                int orig = (int)(0xFFFFFFFFu - (unsigned)k);
                if (lane == 0) {
                    float4 c = scor[pos];
                    float* p = out + OFF_BOX + (size_t)(b * MAXDET + i) * 4;
                    p[0] = c.x; p[1] = c.y; p[2] = c.z; p[3] = c.w;
                    out[OFF_SCORE + b * MAXDET + i] =
                        __uint_as_float((unsigned)(k >> 32));
                }
                const float* cp = class_prob + ((size_t)b * NN + orig) * CC;
                float* co = out + OFF_CLS + (size_t)(b * MAXDET + i) * CC;
                #pragma unroll
                for (int c2 = lane; c2 < CC; c2 += 32) co[c2] = cp[c2];
            }
            if (tid == 0) out[OFF_CNT + b] = (float)MAXDET;
            return;
        }
        needFallback = true;
        __syncthreads();      // everyone done reading hot-path smem
    }

    // ===================== inline exact fallback =============================
    // (statistically never taken; recomputes everything from raw inputs)
    {
        float4* sm4 = (float4*)dyn_smem;     // aliases the hot layout (208KB)

        __shared__ ull  s_wkey[32];
        __shared__ int  s_wslot[32];
        __shared__ ull  s_winkey;
        __shared__ int  s_winslot;
        __shared__ float4 s_ovfbox;
        __shared__ int  s_base;

        if (tid == 0) s_base = 0;
        __syncthreads();
        for (int st = 0; st < NN; st += 1024) {
            int n = st + tid;
            bool p = false;
            float sc = 0.0f;
            if (n < NN) {
                sc = obj[(size_t)b * NN + n];
                p = (sc >= 0.5f);
            }
            unsigned ball = __ballot_sync(0xffffffffu, p);
            int basew = 0;
            if (lane == 0 && ball) basew = atomicAdd(&s_base, __popc(ball));
            basew = __shfl_sync(0xffffffffu, basew, 0);
            if (p) {
                float4 vv = bx4[n];
                float hx = 0.5f * vv.z;
                float hy = 0.5f * vv.w;
                int pos = basew + __popc(ball & ((1u << lane) - 1u));
                g_cor[b][pos]  = make_float4(vv.x - hx, vv.y - hy, vv.x + hx, vv.y + hy);
                g_meta[b][pos] = make_float2(sc, __int_as_float(n));
            }
        }
        __syncthreads();
        const int cnt = s_base;

        ull key[KS];
        unsigned mask = 0u;
        #pragma unroll
        for (int k = 0; k < KS; k++) {
            int slot = (k << 10) + tid;
            key[k] = 0ull;
            if (slot < cnt) {
                sm4[slot] = g_cor[b][slot];
                float2 m = g_meta[b][slot];
                key[k] = ((ull)__float_as_uint(m.x) << 32)
                       | (ull)(0xFFFFFFFFu - __float_as_uint(m.y));
                mask |= (1u << k);
            } else {
                sm4[slot] = make_float4(0.f, 0.f, 0.f, 0.f);
            }
        }
        unsigned mask2 = 0u;
        const int kg_max = (cnt > CAP_S) ? ((cnt - CAP_S + 1023) >> 10) : 0;
        for (int kg = 0; kg < kg_max; kg++) {
            if (CAP_S + (kg << 10) + tid < cnt) mask2 |= (1u << kg);
        }
        __syncthreads();

        float4 W = make_float4(2.f, 2.f, 2.f, 2.f);
        float Wa = 0.f;
        int ndet = 0;

        for (int it = 0; it < MAXDET; it++) {
            ull bk2 = 0ull;
            int bslot = 0;

            #pragma unroll
            for (int k = 0; k < KS; k++) {
                int slot = (k << 10) + tid;
                float4 c = sm4[slot];
                float a2 = (c.z - c.x) * (c.w - c.y);
                if (iou_conflict(W, Wa, c, a2)) mask &= ~(1u << k);
                if (((mask >> k) & 1u) && key[k] > bk2) { bk2 = key[k]; bslot = slot; }
            }
            for (int kg = 0; kg < kg_max; kg++) {
                if ((mask2 >> kg) & 1u) {
                    int slot = CAP_S + (kg << 10) + tid;
                    float4 c = g_cor[b][slot];
                    float a2 = (c.z - c.x) * (c.w - c.y);
                    if (iou_conflict(W, Wa, c, a2)) {
                        mask2 &= ~(1u << kg);
                    } else {
                        float2 m = g_meta[b][slot];
                        ull kk = ((ull)__float_as_uint(m.x) << 32)
                               | (ull)(0xFFFFFFFFu - __float_as_uint(m.y));
                        if (kk > bk2) { bk2 = kk; bslot = slot; }
                    }
                }
            }

            #pragma unroll
            for (int off = 16; off; off >>= 1) {
                ull ok = __shfl_down_sync(0xffffffffu, bk2, off);
                int os = __shfl_down_sync(0xffffffffu, bslot, off);
                if (ok > bk2) { bk2 = ok; bslot = os; }
            }
            if (lane == 0) { s_wkey[wid] = bk2; s_wslot[wid] = bslot; }
            __syncthreads();

            if (wid == 0) {
                ull k2 = s_wkey[lane];
                int sl2 = s_wslot[lane];
                #pragma unroll
                for (int off = 16; off; off >>= 1) {
                    ull ok = __shfl_down_sync(0xffffffffu, k2, off);
                    int os = __shfl_down_sync(0xffffffffu, sl2, off);
                    if (ok > k2) { k2 = ok; sl2 = os; }
                }
                if (lane == 0) { s_winkey = k2; s_winslot = sl2; }
            }
            __syncthreads();

            const ull wk = s_winkey;
            if (wk == 0ull) break;
            const int ws = s_winslot;

            if (ws < CAP_S) {
                W = sm4[ws];
            } else {
                if ((ws & 1023) == tid) s_ovfbox = g_cor[b][ws];
                __syncthreads();
                W = s_ovfbox;
            }
            Wa = (W.z - W.x) * (W.w - W.y);
            ndet = it + 1;

            if (tid == 0) {
                float* p = out + OFF_BOX + (size_t)(b * MAXDET + it) * 4;
                p[0] = W.x; p[1] = W.y; p[2] = W.z; p[3] = W.w;
                out[OFF_SCORE + b * MAXDET + it] =
                    __uint_as_float((unsigned)(wk >> 32));
                winPos[it] = (int)(0xFFFFFFFFu - (unsigned)wk);   // orig idx
            }
            if ((ws & 1023) == tid) {
                if (ws < CAP_S) mask  &= ~(1u << (ws >> 10));
                else            mask2 &= ~(1u << ((ws - CAP_S) >> 10));
            }
        }
        __syncthreads();

        // classes + zero-fill (cold path)
        for (int i = wid; i < MAXDET; i += 32) {
            bool valid = (i < ndet);
            int orig = valid ? winPos[i] : 0;
            if (!valid && lane == 0) {
                float* p = out + OFF_BOX + (size_t)(b * MAXDET + i) * 4;
                p[0] = 0.f; p[1] = 0.f; p[2] = 0.f; p[3] = 0.f;
                out[OFF_SCORE + b * MAXDET + i] = 0.0f;
            }
            const float* cp = class_prob + ((size_t)b * NN + orig) * CC;
            float* co = out + OFF_CLS + (size_t)(b * MAXDET + i) * CC;
            #pragma unroll
            for (int c2 = lane; c2 < CC; c2 += 32) {
                co[c2] = valid ? cp[c2] : 0.0f;
            }
        }
        if (tid == 0) out[OFF_CNT + b] = (float)ndet;
    }
}

// ---------------------------------------------------------------------------
extern "C" void kernel_launch(void* const* d_in, const int* in_sizes, int n_in,
                              void* d_out, int out_size)
{
    const float* boxes = (const float*)d_in[0];   // (16, 25200, 4)
    const float* obj   = (const float*)d_in[1];   // (16, 25200, 1)
    const float* cls   = (const float*)d_in[2];   // (16, 25200, 80)
    float* out = (float*)d_out;

    const int fbSmem  = CAP_S * (int)sizeof(float4);                  // 208KB
    const int hotSmem = SCAP * (int)(sizeof(ull) + sizeof(float4) + sizeof(float))
                      + NB * BCAP * (int)sizeof(ull);                 // ~88KB
    const int smem = (fbSmem > hotSmem) ? fbSmem : hotSmem;

    static bool attr_done = false;
    if (!attr_done) {
        cudaFuncSetAttribute(nms_fused_kernel,
                             cudaFuncAttributeMaxDynamicSharedMemorySize, smem);
        attr_done = true;
    }

    nms_fused_kernel<<<BB, 1024, smem>>>(boxes, obj, cls, out);
}

// round 9
// speedup vs baseline: 1.2533x; 1.0425x over previous
#include <cuda_runtime.h>
#include <stdint.h>

// Problem constants
#define BB 16
#define NN 25200
#define NV 6300              // NN / 4
#define CC 80
#define MAXDET 100

// Bucketed hi-subset (exact prefix of greedy; guarded fallback covers tails)
#define T_BKT 0.95f
#define NB 128               // buckets over [0.95, 1.0)
#define BSCALE 2560.0f       // NB / 0.05
#define BCAP 32              // per-bucket capacity (lambda ~9.8)
#define SCAP 2048            // sorted stream capacity (expected ~1260)
#define WIN 128              // walk window width

// Fallback full list
#define CAP_S 13312
#define KS 13

// Output layout (flattened concat, float32):
#define OFF_BOX   0
#define OFF_SCORE 6400
#define OFF_CLS   8000
#define OFF_CNT   136000

typedef unsigned long long ull;

// ---------------- scratch (__device__ globals: no allocs) -------------------
__device__ int    g_done[BB];
__device__ float4 g_cor[BB][NN];      // fallback-only
__device__ float2 g_meta[BB][NN];     // fallback-only

// identical IOU expression everywhere (proven bit-exact vs reference)
__device__ __forceinline__ bool iou_conflict(float4 A, float aA, float4 B2, float aB)
{
    float ltx = fmaxf(A.x, B2.x);
    float lty = fmaxf(A.y, B2.y);
    float rbx = fminf(A.z, B2.z);
    float rby = fminf(A.w, B2.w);
    float w = fmaxf(rbx - ltx, 0.0f);
    float h = fmaxf(rby - lty, 0.0f);
    float inter = w * h;
    float denom = aA + aB - inter + 1e-9f;
    return inter > 0.5f * denom;
}

extern __shared__ ull dyn_smem[];

// =============================================================================
// HOT kernel: compaction -> bucket sort -> gather -> windowed walk -> write.
// Lean: no fallback code in this function (keeps regs low, no spills).
// Dynamic smem: skey ull[SCAP] | scor float4[SCAP] | sarea float[SCAP]
//               | bkey ull[NB*BCAP]   (~88KB)
// =============================================================================
__global__ void __launch_bounds__(1024, 1)
nms_hot_kernel(const float* __restrict__ boxes, const float* __restrict__ obj,
               const float* __restrict__ class_prob, float* __restrict__ out)
{
    const int b    = blockIdx.x;
    const int tid  = threadIdx.x;
    const int wid  = tid >> 5;
    const int lane = tid & 31;

    ull*    skey  = dyn_smem;                            // [SCAP]
    float4* scor  = (float4*)(dyn_smem + SCAP);          // [SCAP]
    float*  sarea = (float*)(scor + SCAP);               // [SCAP]
    ull*    bkey  = (ull*)(sarea + SCAP);                // [NB*BCAP]

    __shared__ int      s_cnt[NB];
    __shared__ int      s_off[NB];
    __shared__ int      s_ws[4];
    __shared__ int      s_len;
    __shared__ int      s_bad;
    __shared__ unsigned srow[WIN][4];
    __shared__ unsigned sconfA[4];
    __shared__ int      winPos[MAXDET];
    __shared__ float4   acor[MAXDET];
    __shared__ float    aarea[MAXDET];
    __shared__ int      s_accN;

    const float4* bx4  = reinterpret_cast<const float4*>(boxes) + (size_t)b * NN;
    const float4* obj4 = reinterpret_cast<const float4*>(obj) + (size_t)b * NV;

    // ================= phase A: smem bucket compaction =======================
    if (tid < NB) s_cnt[tid] = 0;
    if (tid < 4) sconfA[tid] = 0;
    if (tid == 0) { s_bad = 0; s_accN = 0; }
    __syncthreads();

    for (int i = tid; i < NV; i += 1024) {
        float4 s4 = obj4[i];
        #pragma unroll
        for (int j = 0; j < 4; j++) {
            float sc = (j == 0) ? s4.x : (j == 1) ? s4.y : (j == 2) ? s4.z : s4.w;
            if (sc >= T_BKT) {
                int n = i * 4 + j;
                int bk = (int)((sc - T_BKT) * BSCALE);
                bk = bk > (NB - 1) ? (NB - 1) : (bk < 0 ? 0 : bk);
                int pos = atomicAdd(&s_cnt[bk], 1);
                if (pos < BCAP) {
                    bkey[bk * BCAP + pos] = ((ull)__float_as_uint(sc) << 32)
                                          | (ull)(0xFFFFFFFFu - (unsigned)n);
                } else {
                    s_bad = 1;
                }
            }
        }
    }
    __syncthreads();

    // ================= phase B: descending-bucket offsets ====================
    int x = 0, v = 0;
    if (tid < NB) {
        v = s_cnt[NB - 1 - tid];
        x = v;
        #pragma unroll
        for (int o = 1; o < 32; o <<= 1) {
            int y = __shfl_up_sync(0xffffffffu, x, o);
            if (lane >= o) x += y;
        }
        if (lane == 31) s_ws[wid] = x;
    }
    __syncthreads();
    if (tid < NB) {
        int add = 0;
        #pragma unroll
        for (int w = 0; w < 4; w++) if (w < wid) add += s_ws[w];
        int incl = x + add;
        s_off[NB - 1 - tid] = incl - v;
        if (tid == NB - 1) s_len = incl;
    }
    __syncthreads();

    const int streamLen = s_len;
    if (s_bad || streamLen > SCAP) {
        if (tid == 0) g_done[b] = 0;
        return;
    }

    // ============ phase C: per-bucket in-warp bitonic sort32 =================
    for (int bk = wid; bk < NB; bk += 32) {
        int n = s_cnt[bk];
        if (n == 0) continue;
        ull k = (lane < n) ? ~bkey[bk * BCAP + lane] : ~0ull;  // asc(~k)==desc(k)
        #pragma unroll
        for (int sz = 2; sz <= 32; sz <<= 1) {
            #pragma unroll
            for (int j = sz >> 1; j > 0; j >>= 1) {
                ull pk = __shfl_xor_sync(0xffffffffu, k, j);
                bool up = ((lane & sz) == 0);
                bool takeMax = (((lane & j) != 0) == up);
                if (takeMax ? (pk > k) : (pk < k)) k = pk;
            }
        }
        if (lane < n) skey[s_off[bk] + lane] = ~k;
    }
    __syncthreads();

    // ============ phase D: gather corners + precompute areas =================
    for (int i = tid; i < streamLen; i += 1024) {
        int idx = (int)(0xFFFFFFFFu - (unsigned)skey[i]);
        float4 vv = bx4[idx];                       // (x, y, w, h)
        float hx = 0.5f * vv.z;
        float hy = 0.5f * vv.w;
        float4 c = make_float4(vv.x - hx, vv.y - hy, vv.x + hx, vv.y + hy);
        scor[i] = c;
        sarea[i] = (c.z - c.x) * (c.w - c.y);
    }
    __syncthreads();

    // ============ phase E: alive-filtered windowed greedy walk ===============
    const int r  = tid >> 3;      // 0..127 (window row)
    const int g8 = tid & 7;       // 0..7
    int accN = 0;

    for (int base = 0; base < streamLen && accN < MAXDET; base += WIN) {
        const int wcnt = (streamLen - base < WIN) ? (streamLen - base) : WIN;

        const bool rvalid = (r < wcnt);
        float4 cr = make_float4(0.f, 0.f, 0.f, 0.f);
        float  ar = 0.0f;
        if (rvalid) { cr = scor[base + r]; ar = sarea[base + r]; }

        // -- pass 1: conflicts vs previously accepted (8 threads/row) ---------
        bool conf = false;
        if (rvalid) {
            for (int a = g8; a < accN; a += 8) {
                if (iou_conflict(acor[a], aarea[a], cr, ar)) conf = true;
            }
        }
        unsigned bl = __ballot_sync(0xffffffffu, conf);
        if ((lane & 7) == 0) {
            if (((bl >> lane) & 0xffu) != 0u)
                atomicOr(&sconfA[r >> 5], 1u << (r & 31));
        }
        __syncthreads();                                           // B1

        // -- alive bitmap (dead = conflicted OR >= wcnt) ----------------------
        unsigned dead[4];
        #pragma unroll
        for (int w2 = 0; w2 < 4; w2++) {
            unsigned vm;
            int lo = w2 << 5;
            if (wcnt >= lo + 32) vm = 0xffffffffu;
            else if (wcnt <= lo) vm = 0u;
            else vm = (1u << (wcnt - lo)) - 1u;
            dead[w2] = sconfA[w2] | ~vm;
        }
        const bool ralive = rvalid && !((dead[r >> 5] >> (r & 31)) & 1u);

        // -- pass 2: pairwise rows, alive x alive; unconditional write --------
        unsigned bits = 0u;
        if (ralive) {
            int c0 = g8 * 16;
            #pragma unroll
            for (int j = 0; j < 16; j++) {
                int col = c0 + j;
                if (!((dead[col >> 5] >> (col & 31)) & 1u) && col != r) {
                    if (iou_conflict(cr, ar, scor[base + col], sarea[base + col]))
                        bits |= (1u << j);
                }
            }
        }
        unsigned hibits = __shfl_down_sync(0xffffffffu, bits, 1);
        if ((g8 & 1) == 0) srow[r][g8 >> 1] = bits | (hibits << 16);
        __syncthreads();                                           // B2

        // -- serial exact resolve (tid 0): indices only -----------------------
        if (tid == 0) {
            unsigned alive[4];
            #pragma unroll
            for (int w2 = 0; w2 < 4; w2++) alive[w2] = ~dead[w2];
            int acc = accN;
            #pragma unroll
            for (int w2 = 0; w2 < 4; w2++) {
                unsigned a = alive[w2];
                while (a && acc < MAXDET) {
                    int bit = __ffs(a) - 1;
                    a &= a - 1;
                    int i = (w2 << 5) + bit;
                    winPos[acc++] = base + i;
                    a &= ~srow[i][w2];
                    #pragma unroll
                    for (int w3 = 1; w3 < 4; w3++)
                        if (w3 > w2) alive[w3] &= ~srow[i][w3];
                }
                if (acc >= MAXDET) break;
            }
            s_accN = acc;
        }
        __syncthreads();                                           // B3

        // -- parallel copy of new accepts + clear sconfA for next window ------
        int newN = s_accN;
        for (int i = accN + tid; i < newN; i += 1024) {
            int sp = winPos[i];
            acor[i] = scor[sp];
            aarea[i] = sarea[sp];
        }
        if (tid < 4) sconfA[tid] = 0;
        __syncthreads();                                           // B4
        accN = newN;
    }

    if (tid == 0) g_done[b] = (accN == MAXDET) ? 1 : 0;
    if (accN != MAXDET) return;                 // fallback produces output

    // ============ phase F: fused output write (hot path) =====================
    for (int i = wid; i < MAXDET; i += 32) {
        int pos = winPos[i];
        ull k = skey[pos];
        int orig = (int)(0xFFFFFFFFu - (unsigned)k);
        if (lane == 0) {
            float4 c = scor[pos];
            float* p = out + OFF_BOX + (size_t)(b * MAXDET + i) * 4;
            p[0] = c.x; p[1] = c.y; p[2] = c.z; p[3] = c.w;
            out[OFF_SCORE + b * MAXDET + i] = __uint_as_float((unsigned)(k >> 32));
        }
        const float* cp = class_prob + ((size_t)b * NN + orig) * CC;
        float* co = out + OFF_CLS + (size_t)(b * MAXDET + i) * CC;
        #pragma unroll
        for (int c2 = lane; c2 < CC; c2 += 32) co[c2] = cp[c2];
    }
    if (tid == 0) out[OFF_CNT + b] = (float)MAXDET;
}

// =============================================================================
// FALLBACK kernel (guarded by g_done; statistically never runs the slow path).
// Recompacts from raw inputs, proven exact round machinery, writes outputs.
// Dynamic smem: float4[CAP_S] (208KB)
// =============================================================================
__global__ void __launch_bounds__(1024, 1)
nms_fallback_kernel(const float* __restrict__ boxes, const float* __restrict__ obj,
                    const float* __restrict__ class_prob, float* __restrict__ out)
{
    const int b = blockIdx.x;
    if (g_done[b]) return;

    const int tid  = threadIdx.x;
    const int wid  = tid >> 5;
    const int lane = tid & 31;

    float4* sm4 = (float4*)dyn_smem;

    __shared__ ull  s_wkey[32];
    __shared__ int  s_wslot[32];
    __shared__ ull  s_winkey;
    __shared__ int  s_winslot;
    __shared__ float4 s_ovfbox;
    __shared__ int  s_base;
    __shared__ int  s_orig[MAXDET];

    const float4* bx4 = reinterpret_cast<const float4*>(boxes) + (size_t)b * NN;

    if (tid == 0) s_base = 0;
    __syncthreads();
    for (int st = 0; st < NN; st += 1024) {
        int n = st + tid;
        bool p = false;
        float sc = 0.0f;
        if (n < NN) {
            sc = obj[(size_t)b * NN + n];
            p = (sc >= 0.5f);
        }
        unsigned ball = __ballot_sync(0xffffffffu, p);
        int basew = 0;
        if (lane == 0 && ball) basew = atomicAdd(&s_base, __popc(ball));
        basew = __shfl_sync(0xffffffffu, basew, 0);
        if (p) {
            float4 vv = bx4[n];
            float hx = 0.5f * vv.z;
            float hy = 0.5f * vv.w;
            int pos = basew + __popc(ball & ((1u << lane) - 1u));
            g_cor[b][pos]  = make_float4(vv.x - hx, vv.y - hy, vv.x + hx, vv.y + hy);
            g_meta[b][pos] = make_float2(sc, __int_as_float(n));
        }
    }
    __syncthreads();
    const int cnt = s_base;

    ull key[KS];
    unsigned mask = 0u;
    #pragma unroll
    for (int k = 0; k < KS; k++) {
        int slot = (k << 10) + tid;
        key[k] = 0ull;
        if (slot < cnt) {
            sm4[slot] = g_cor[b][slot];
            float2 m = g_meta[b][slot];
            key[k] = ((ull)__float_as_uint(m.x) << 32)
                   | (ull)(0xFFFFFFFFu - __float_as_uint(m.y));
            mask |= (1u << k);
        } else {
            sm4[slot] = make_float4(0.f, 0.f, 0.f, 0.f);
        }
    }
    unsigned mask2 = 0u;
    const int kg_max = (cnt > CAP_S) ? ((cnt - CAP_S + 1023) >> 10) : 0;
    for (int kg = 0; kg < kg_max; kg++) {
        if (CAP_S + (kg << 10) + tid < cnt) mask2 |= (1u << kg);
    }
    __syncthreads();

    float4 W = make_float4(2.f, 2.f, 2.f, 2.f);
    float Wa = 0.f;
    int ndet = 0;

    for (int it = 0; it < MAXDET; it++) {
        ull bk2 = 0ull;
        int bslot = 0;

        #pragma unroll
        for (int k = 0; k < KS; k++) {
            int slot = (k << 10) + tid;
            float4 c = sm4[slot];
            float a2 = (c.z - c.x) * (c.w - c.y);
            if (iou_conflict(W, Wa, c, a2)) mask &= ~(1u << k);
            if (((mask >> k) & 1u) && key[k] > bk2) { bk2 = key[k]; bslot = slot; }
        }
        for (int kg = 0; kg < kg_max; kg++) {
            if ((mask2 >> kg) & 1u) {
                int slot = CAP_S + (kg << 10) + tid;
                float4 c = g_cor[b][slot];
                float a2 = (c.z - c.x) * (c.w - c.y);
                if (iou_conflict(W, Wa, c, a2)) {
                    mask2 &= ~(1u << kg);
                } else {
                    float2 m = g_meta[b][slot];
                    ull kk = ((ull)__float_as_uint(m.x) << 32)
                           | (ull)(0xFFFFFFFFu - __float_as_uint(m.y));
                    if (kk > bk2) { bk2 = kk; bslot = slot; }
                }
            }
        }

        #pragma unroll
        for (int off = 16; off; off >>= 1) {
            ull ok = __shfl_down_sync(0xffffffffu, bk2, off);
            int os = __shfl_down_sync(0xffffffffu, bslot, off);
            if (ok > bk2) { bk2 = ok; bslot = os; }
        }
        if (lane == 0) { s_wkey[wid] = bk2; s_wslot[wid] = bslot; }
        __syncthreads();

        if (wid == 0) {
            ull k2 = s_wkey[lane];
            int sl2 = s_wslot[lane];
            #pragma unroll
            for (int off = 16; off; off >>= 1) {
                ull ok = __shfl_down_sync(0xffffffffu, k2, off);
                int os = __shfl_down_sync(0xffffffffu, sl2, off);
                if (ok > k2) { k2 = ok; sl2 = os; }
            }
            if (lane == 0) { s_winkey = k2; s_winslot = sl2; }
        }
        __syncthreads();

        const ull wk = s_winkey;
        if (wk == 0ull) break;
        const int ws = s_winslot;

        if (ws < CAP_S) {
            W = sm4[ws];
        } else {
            if ((ws & 1023) == tid) s_ovfbox = g_cor[b][ws];
            __syncthreads();
            W = s_ovfbox;
        }
        Wa = (W.z - W.x) * (W.w - W.y);
        ndet = it + 1;

        if (tid == 0) {
            float* p = out + OFF_BOX + (size_t)(b * MAXDET + it) * 4;
            p[0] = W.x; p[1] = W.y; p[2] = W.z; p[3] = W.w;
            out[OFF_SCORE + b * MAXDET + it] =
                __uint_as_float((unsigned)(wk >> 32));
            s_orig[it] = (int)(0xFFFFFFFFu - (unsigned)wk);
        }
        if ((ws & 1023) == tid) {
            if (ws < CAP_S) mask  &= ~(1u << (ws >> 10));
            else            mask2 &= ~(1u << ((ws - CAP_S) >> 10));
        }
    }
    __syncthreads();

    for (int i = wid; i < MAXDET; i += 32) {
        bool valid = (i < ndet);
        int orig = valid ? s_orig[i] : 0;
        if (!valid && lane == 0) {
            float* p = out + OFF_BOX + (size_t)(b * MAXDET + i) * 4;
            p[0] = 0.f; p[1] = 0.f; p[2] = 0.f; p[3] = 0.f;
            out[OFF_SCORE + b * MAXDET + i] = 0.0f;
        }
        const float* cp = class_prob + ((size_t)b * NN + orig) * CC;
        float* co = out + OFF_CLS + (size_t)(b * MAXDET + i) * CC;
        #pragma unroll
        for (int c2 = lane; c2 < CC; c2 += 32) {
            co[c2] = valid ? cp[c2] : 0.0f;
        }
    }
    if (tid == 0) out[OFF_CNT + b] = (float)ndet;
}

// ---------------------------------------------------------------------------
extern "C" void kernel_launch(void* const* d_in, const int* in_sizes, int n_in,
                              void* d_out, int out_size)
{
    const float* boxes = (const float*)d_in[0];   // (16, 25200, 4)
    const float* obj   = (const float*)d_in[1];   // (16, 25200, 1)
    const float* cls   = (const float*)d_in[2];   // (16, 25200, 80)
    float* out = (float*)d_out;

    const int hotSmem = SCAP * (int)(sizeof(ull) + sizeof(float4) + sizeof(float))
                      + NB * BCAP * (int)sizeof(ull);                 // ~88KB
    const int fbSmem  = CAP_S * (int)sizeof(float4);                  // 208KB

    static bool attr_done = false;
    if (!attr_done) {
        cudaFuncSetAttribute(nms_hot_kernel,
                             cudaFuncAttributeMaxDynamicSharedMemorySize, hotSmem);
        cudaFuncSetAttribute(nms_fallback_kernel,
                             cudaFuncAttributeMaxDynamicSharedMemorySize, fbSmem);
        attr_done = true;
    }

    nms_hot_kernel<<<BB, 1024, hotSmem>>>(boxes, obj, cls, out);
    nms_fallback_kernel<<<BB, 1024, fbSmem>>>(boxes, obj, cls, out);
}